// round 4
// baseline (speedup 1.0000x reference)
#include <cuda_runtime.h>
#include <cstdint>

#define NF   40
#define ED   128
#define AD   128
#define NP   780     // 40*39/2
#define NPP  784     // padded to 98 n-tiles of 8 pairs
#define NTHR 384     // 12 warps = 3 pair-groups x 4 a-slots
#define NWRP 12
#define XST  132     // padded row stride for x in smem (floats); 528B = 33*16B

__device__ __forceinline__ uint32_t tf32_of(float f) {
    uint32_t r;
    asm("cvt.rna.tf32.f32 %0, %1;" : "=r"(r) : "f"(f));
    return r;
}

// D(m16n8) += A(m16k8, tf32, row) * B(k8n8, tf32, col), fp32 accum
__device__ __forceinline__ void mma8(float* d, const uint32_t* a, uint32_t b0, uint32_t b1) {
    asm volatile(
        "mma.sync.aligned.m16n8k8.row.col.f32.tf32.tf32.f32 "
        "{%0,%1,%2,%3}, {%4,%5,%6,%7}, {%8,%9}, {%0,%1,%2,%3};"
        : "+f"(d[0]), "+f"(d[1]), "+f"(d[2]), "+f"(d[3])
        : "r"(a[0]), "r"(a[1]), "r"(a[2]), "r"(a[3]), "r"(b0), "r"(b1));
}

// e-permutation: MMA k-step s, k-offset kappa, thread col c:
//   b0 (kappa=c)   <-> e = c*32 + 2s
//   b1 (kappa=c+4) <-> e = c*32 + 2s + 1
// x smem layout: within a row, 16B chunk ch (= e>>2) stored at slot ch ^ (ch>>3).
__device__ __forceinline__ int xslot_off(int e) {
    int ch = e >> 2;
    return ((ch ^ (ch >> 3)) << 2) | (e & 3);
}

__global__ void __launch_bounds__(NTHR, 1)
afm_kernel(const float* __restrict__ x,    // [B, F, E]
           const float* __restrict__ ww,   // [A, E]
           const float* __restrict__ wb,   // [A]
           const float* __restrict__ hw,   // [1, A]
           const float* __restrict__ pw,   // [1, E]
           const float* __restrict__ pb,   // [1]
           float* __restrict__ out)        // [B]
{
    __shared__ float   xs[NF * XST];      // ~21.1 KB, chunk-swizzled rows
    __shared__ float   scs4[4][NPP];      // per-aslot partial scores
    __shared__ float   scs[NPP];
    __shared__ float   dvs[NPP];          // d[p] = hp_p . p_w
    __shared__ float   pws[ED];
    __shared__ uint8_t pis[NPP], pjs[NPP];
    __shared__ float   red[3 * NWRP];

    const int tid  = threadIdx.x;
    const int wid  = tid >> 5, lane = tid & 31;
    const int g     = wid >> 2;       // pair-group 0..2
    const int aslot = wid & 3;        // owns a-rows [aslot*32, aslot*32+32)
    const int q = lane >> 2, c = lane & 3;
    const int b = blockIdx.x;

    // ---- Stage x into chunk-swizzled smem ----
    const float* xg = x + (size_t)b * (NF * ED);
    for (int idx = tid; idx < NF * ED; idx += NTHR) {
        int row = idx >> 7, e = idx & 127;
        xs[row * XST + xslot_off(e)] = xg[idx];
    }
    for (int e = tid; e < ED; e += NTHR) pws[e] = pw[e];

    // ---- Pair index tables (triu i<j, i-major) ----
    for (int p = tid; p < NPP; p += NTHR) {
        if (p < NP) {
            int i = 0, rem = p;
            while (rem >= NF - 1 - i) { rem -= NF - 1 - i; i++; }
            pis[p] = (uint8_t)i; pjs[p] = (uint8_t)(i + 1 + rem);
        } else { pis[p] = 0; pjs[p] = 1; }
    }

    // ---- W fragments (register-stationary, e-permuted to match B build) ----
    const int A0 = aslot * 32;
    uint32_t wA[2][16][4];
    #pragma unroll
    for (int mt = 0; mt < 2; mt++) {
        #pragma unroll
        for (int s = 0; s < 16; s++) {
            int r0 = (A0 + mt * 16 + q) * ED + c * 32 + 2 * s;
            int r1 = r0 + 8 * ED;
            float2 w0 = *(const float2*)&ww[r0];
            float2 w1 = *(const float2*)&ww[r1];
            wA[mt][s][0] = tf32_of(w0.x);
            wA[mt][s][1] = tf32_of(w1.x);
            wA[mt][s][2] = tf32_of(w0.y);
            wA[mt][s][3] = tf32_of(w1.y);
        }
    }
    float wbr[4], hr[4];
    #pragma unroll
    for (int u = 0; u < 4; u++) {
        wbr[u] = wb[A0 + u * 8 + q];
        hr[u]  = hw[A0 + u * 8 + q];
    }

    __syncthreads();

    // ---- Main loop: n-tiles of 8 pairs; group g covers [g*33, min(g*33+33, 98)) ----
    const int nt0 = g * 33;
    const int nt1 = (g == 2) ? 98 : nt0 + 33;
    for (int nt = nt0; nt < nt1; nt++) {
        const int p = nt * 8 + q;                 // this quad's pair (B col)
        // thread c's 32-float e-run starts at chunk c*8 (c*32 floats)
        const float4* xi4 = (const float4*)&xs[(int)pis[p] * XST + c * 32];
        const float4* xj4 = (const float4*)&xs[(int)pjs[p] * XST + c * 32];

        float acc0[4] = {0.f, 0.f, 0.f, 0.f};
        float acc1[4] = {0.f, 0.f, 0.f, 0.f};
        #pragma unroll
        for (int w = 0; w < 8; w++) {
            // chunk c*8+w lives at slot index (w^c) within this thread's block
            float4 vi = xi4[w ^ c];
            float4 vj = xj4[w ^ c];
            // raw f32 bits as tf32 (HW truncates mantissa)
            uint32_t b0 = __float_as_uint(vi.x * vj.x);
            uint32_t b1 = __float_as_uint(vi.y * vj.y);
            uint32_t b2 = __float_as_uint(vi.z * vj.z);
            uint32_t b3 = __float_as_uint(vi.w * vj.w);
            mma8(acc0, wA[0][2 * w],     b0, b1);
            mma8(acc1, wA[1][2 * w],     b0, b1);
            mma8(acc0, wA[0][2 * w + 1], b2, b3);
            mma8(acc1, wA[1][2 * w + 1], b2, b3);
        }

        // Fused epilogue: partial score = sum over this warp's 32 a of h*relu(.+wb)
        float s0 = fmaxf(acc0[0] + wbr[0], 0.f) * hr[0]
                 + fmaxf(acc0[2] + wbr[1], 0.f) * hr[1]
                 + fmaxf(acc1[0] + wbr[2], 0.f) * hr[2]
                 + fmaxf(acc1[2] + wbr[3], 0.f) * hr[3];
        float s1 = fmaxf(acc0[1] + wbr[0], 0.f) * hr[0]
                 + fmaxf(acc0[3] + wbr[1], 0.f) * hr[1]
                 + fmaxf(acc1[1] + wbr[2], 0.f) * hr[2]
                 + fmaxf(acc1[3] + wbr[3], 0.f) * hr[3];
        #pragma unroll
        for (int o = 4; o <= 16; o <<= 1) {
            s0 += __shfl_xor_sync(0xffffffffu, s0, o);
            s1 += __shfl_xor_sync(0xffffffffu, s1, o);
        }
        if (lane < 4) {
            scs4[aslot][nt * 8 + 2 * lane]     = s0;
            scs4[aslot][nt * 8 + 2 * lane + 1] = s1;
        }
    }

    // ---- d[p] = sum_e x_i,e * x_j,e * pw_e (warp per pair; swizzle-aware) ----
    for (int p = wid; p < NP; p += NWRP) {
        const float* xi = &xs[(int)pis[p] * XST];
        const float* xj = &xs[(int)pjs[p] * XST];
        float a = 0.f;
        #pragma unroll
        for (int k = 0; k < 4; k++) {
            int e = lane + 32 * k;
            int off = xslot_off(e);
            a = fmaf(xi[off] * xj[off], pws[e], a);
        }
        #pragma unroll
        for (int o = 16; o; o >>= 1) a += __shfl_xor_sync(0xffffffffu, a, o);
        if (lane == 0) dvs[p] = a;
    }
    __syncthreads();

    for (int p = tid; p < NP; p += NTHR)
        scs[p] = scs4[0][p] + scs4[1][p] + scs4[2][p] + scs4[3][p];
    __syncthreads();

    // ---- Softmax over pairs + weighted sum (h_b softmax-invariant, dropped) ----
    float lmax = -3.4e38f;
    for (int p = tid; p < NP; p += NTHR) lmax = fmaxf(lmax, scs[p]);
    #pragma unroll
    for (int o = 16; o; o >>= 1) lmax = fmaxf(lmax, __shfl_xor_sync(0xffffffffu, lmax, o));
    if (lane == 0) red[wid] = lmax;
    __syncthreads();
    float m = red[0];
    #pragma unroll
    for (int w = 1; w < NWRP; w++) m = fmaxf(m, red[w]);

    float se = 0.f, sd = 0.f;
    for (int p = tid; p < NP; p += NTHR) {
        float e = __expf(scs[p] - m);
        se += e;
        sd = fmaf(e, dvs[p], sd);
    }
    #pragma unroll
    for (int o = 16; o; o >>= 1) {
        se += __shfl_xor_sync(0xffffffffu, se, o);
        sd += __shfl_xor_sync(0xffffffffu, sd, o);
    }
    if (lane == 0) { red[NWRP + wid] = se; red[2 * NWRP + wid] = sd; }
    __syncthreads();
    if (tid == 0) {
        float S = 0.f, D = 0.f;
        #pragma unroll
        for (int w = 0; w < NWRP; w++) { S += red[NWRP + w]; D += red[2 * NWRP + w]; }
        out[b] = D / S + pb[0];
    }
}

extern "C" void kernel_launch(void* const* d_in, const int* in_sizes, int n_in,
                              void* d_out, int out_size) {
    const float* x  = (const float*)d_in[0];
    const float* ww = (const float*)d_in[1];
    const float* wb = (const float*)d_in[2];
    const float* hw = (const float*)d_in[3];
    // d_in[4] = attn_h_b: uniform shift on scores, softmax-invariant -> unused
    const float* pw = (const float*)d_in[5];
    const float* pb = (const float*)d_in[6];
    float* out = (float*)d_out;

    int B = in_sizes[0] / (NF * ED);
    afm_kernel<<<B, NTHR>>>(x, ww, wb, hw, pw, pb, out);
}

// round 5
// speedup vs baseline: 1.0099x; 1.0099x over previous
#include <cuda_runtime.h>
#include <cstdint>

#define NF   40
#define ED   128
#define AD   128
#define NP   780     // 40*39/2
#define NPP  784     // 98 n-tiles of 8 pairs
#define NTILE 98
#define NTHR 384     // 12 warps = 3 groups x 2 aslots x 2 khalves
#define NWRP 12
#define XST  132     // padded row stride for x in smem (floats)

// ---- dynamic smem offsets (bytes) ----
#define OFF_XS    0        // 40*132*4 = 21120
#define OFF_ACC   21120    // 6 pairids * 2 parity * 32 lanes * 16 f = 24576
#define OFF_SCS2  45696    // 2 * 784 * 4 = 6272
#define OFF_SCS   51968    // 784*4
#define OFF_DVS   55104    // 784*4
#define OFF_PWS   58240    // 128*4
#define OFF_PIS   58752    // 784
#define OFF_PJS   59540    // 784
#define OFF_RED   60328    // 3*12*4 = 144
#define SMEM_SZ   60480

__device__ __forceinline__ uint32_t tf32_of(float f) {
    uint32_t r;
    asm("cvt.rna.tf32.f32 %0, %1;" : "=r"(r) : "f"(f));
    return r;
}

// D(m16n8) += A(m16k8, tf32, row) * B(k8n8, tf32, col), fp32 accum
__device__ __forceinline__ void mma8(float* d, const uint32_t* a, uint32_t b0, uint32_t b1) {
    asm volatile(
        "mma.sync.aligned.m16n8k8.row.col.f32.tf32.tf32.f32 "
        "{%0,%1,%2,%3}, {%4,%5,%6,%7}, {%8,%9}, {%0,%1,%2,%3};"
        : "+f"(d[0]), "+f"(d[1]), "+f"(d[2]), "+f"(d[3])
        : "r"(a[0]), "r"(a[1]), "r"(a[2]), "r"(a[3]), "r"(b0), "r"(b1));
}

__global__ void __launch_bounds__(NTHR, 1)
afm_kernel(const float* __restrict__ x,    // [B, F, E]
           const float* __restrict__ ww,   // [A, E]
           const float* __restrict__ wb,   // [A]
           const float* __restrict__ hw,   // [1, A]
           const float* __restrict__ pw,   // [1, E]
           const float* __restrict__ pb,   // [1]
           float* __restrict__ out)        // [B]
{
    extern __shared__ char smem[];
    float*   xs   = (float*)(smem + OFF_XS);
    float*   accb = (float*)(smem + OFF_ACC);
    float*   scs2 = (float*)(smem + OFF_SCS2);   // [2][NPP]
    float*   scs  = (float*)(smem + OFF_SCS);
    float*   dvs  = (float*)(smem + OFF_DVS);
    float*   pws  = (float*)(smem + OFF_PWS);
    uint8_t* pis  = (uint8_t*)(smem + OFF_PIS);
    uint8_t* pjs  = (uint8_t*)(smem + OFF_PJS);
    float*   red  = (float*)(smem + OFF_RED);

    const int tid  = threadIdx.x;
    const int wid  = tid >> 5, lane = tid & 31;
    const int g      = wid >> 2;        // pair-group 0..2
    const int aslot  = (wid >> 1) & 1;  // a-rows [aslot*64, +64)
    const int kh     = wid & 1;         // k-half: e in [kh*64, +64)
    const int pairid = g * 2 + aslot;   // 0..5 (accbuf slab / named barrier)
    const int q = lane >> 2, c = lane & 3;
    const int b = blockIdx.x;

    // ---- Stage x (row-major, padded stride) ----
    const float* xg = x + (size_t)b * (NF * ED);
    for (int idx = tid; idx < NF * ED; idx += NTHR)
        xs[(idx >> 7) * XST + (idx & 127)] = xg[idx];
    for (int e = tid; e < ED; e += NTHR) pws[e] = pw[e];

    // ---- Pair index tables (triu i<j, i-major) ----
    for (int p = tid; p < NPP; p += NTHR) {
        if (p < NP) {
            int i = 0, rem = p;
            while (rem >= NF - 1 - i) { rem -= NF - 1 - i; i++; }
            pis[p] = (uint8_t)i; pjs[p] = (uint8_t)(i + 1 + rem);
        } else { pis[p] = 0; pjs[p] = 1; }
    }

    // ---- W fragments: 64 a-rows x 64 e  -> 4 m-tiles x 8 s x 4 regs = 128 ----
    const int A0 = aslot * 64;
    const int E0 = kh * 64;
    uint32_t wA[4][8][4];
    #pragma unroll
    for (int mt = 0; mt < 4; mt++) {
        #pragma unroll
        for (int s = 0; s < 8; s++) {
            int r0 = (A0 + mt * 16 + q) * ED + E0 + s * 8 + c;
            int r1 = r0 + 8 * ED;
            wA[mt][s][0] = tf32_of(ww[r0]);
            wA[mt][s][1] = tf32_of(ww[r1]);
            wA[mt][s][2] = tf32_of(ww[r0 + 4]);
            wA[mt][s][3] = tf32_of(ww[r1 + 4]);
        }
    }
    __syncthreads();

    // ---- Main loop over this group's n-tiles ----
    const int nt0 = g * 33;
    const int nt1 = (g == 2) ? NTILE : nt0 + 33;
    float* myacc = &accb[(size_t)pairid * 2 * 32 * 16 + lane * 16];  // + parity*512

    for (int nt = nt0; nt < nt1; nt++) {
        const int p = nt * 8 + q;
        const float* xi = &xs[(int)pis[p] * XST + E0 + c];
        const float* xj = &xs[(int)pjs[p] * XST + E0 + c];

        float acc[4][4] = {};
        #pragma unroll
        for (int s = 0; s < 8; s++) {
            uint32_t b0 = __float_as_uint(xi[8 * s]     * xj[8 * s]);
            uint32_t b1 = __float_as_uint(xi[8 * s + 4] * xj[8 * s + 4]);
            mma8(acc[0], wA[0][s], b0, b1);
            mma8(acc[1], wA[1][s], b0, b1);
            mma8(acc[2], wA[2][s], b0, b1);
            mma8(acc[3], wA[3][s], b0, b1);
        }

        float* buf = myacc + (nt & 1) * 512;  // 32 lanes * 16 floats

        if (kh == 1) {
            // partner writes its partial accums, then syncs
            #pragma unroll
            for (int mt = 0; mt < 4; mt++)
                *(float4*)&buf[mt * 4] = make_float4(acc[mt][0], acc[mt][1], acc[mt][2], acc[mt][3]);
            asm volatile("bar.sync %0, 64;" :: "r"(1 + pairid) : "memory");
        } else {
            asm volatile("bar.sync %0, 64;" :: "r"(1 + pairid) : "memory");
            float s0 = 0.f, s1 = 0.f;
            #pragma unroll
            for (int mt = 0; mt < 4; mt++) {
                float4 o = *(const float4*)&buf[mt * 4];
                int a0 = A0 + mt * 16 + q, a1 = a0 + 8;
                float wb0 = wb[a0], h0 = hw[a0];
                float wb1 = wb[a1], h1 = hw[a1];
                s0 += fmaxf(acc[mt][0] + o.x + wb0, 0.f) * h0
                    + fmaxf(acc[mt][2] + o.z + wb1, 0.f) * h1;
                s1 += fmaxf(acc[mt][1] + o.y + wb0, 0.f) * h0
                    + fmaxf(acc[mt][3] + o.w + wb1, 0.f) * h1;
            }
            #pragma unroll
            for (int o = 4; o <= 16; o <<= 1) {
                s0 += __shfl_xor_sync(0xffffffffu, s0, o);
                s1 += __shfl_xor_sync(0xffffffffu, s1, o);
            }
            if (lane < 4) {
                scs2[aslot * NPP + nt * 8 + 2 * lane]     = s0;
                scs2[aslot * NPP + nt * 8 + 2 * lane + 1] = s1;
            }
        }
    }

    // ---- d[p] = sum_e x_i,e * x_j,e * pw_e (warp per pair) ----
    for (int p = wid; p < NP; p += NWRP) {
        const float* xi = &xs[(int)pis[p] * XST];
        const float* xj = &xs[(int)pjs[p] * XST];
        float a = 0.f;
        #pragma unroll
        for (int k = 0; k < 4; k++) {
            int e = lane + 32 * k;
            a = fmaf(xi[e] * xj[e], pws[e], a);
        }
        #pragma unroll
        for (int o = 16; o; o >>= 1) a += __shfl_xor_sync(0xffffffffu, a, o);
        if (lane == 0) dvs[p] = a;
    }
    __syncthreads();

    for (int p = tid; p < NP; p += NTHR)
        scs[p] = scs2[p] + scs2[NPP + p];
    __syncthreads();

    // ---- Softmax over pairs + weighted sum (h_b softmax-invariant, dropped) ----
    float lmax = -3.4e38f;
    for (int p = tid; p < NP; p += NTHR) lmax = fmaxf(lmax, scs[p]);
    #pragma unroll
    for (int o = 16; o; o >>= 1) lmax = fmaxf(lmax, __shfl_xor_sync(0xffffffffu, lmax, o));
    if (lane == 0) red[wid] = lmax;
    __syncthreads();
    float m = red[0];
    #pragma unroll
    for (int w = 1; w < NWRP; w++) m = fmaxf(m, red[w]);

    float se = 0.f, sd = 0.f;
    for (int p = tid; p < NP; p += NTHR) {
        float e = __expf(scs[p] - m);
        se += e;
        sd = fmaf(e, dvs[p], sd);
    }
    #pragma unroll
    for (int o = 16; o; o >>= 1) {
        se += __shfl_xor_sync(0xffffffffu, se, o);
        sd += __shfl_xor_sync(0xffffffffu, sd, o);
    }
    if (lane == 0) { red[NWRP + wid] = se; red[2 * NWRP + wid] = sd; }
    __syncthreads();
    if (tid == 0) {
        float S = 0.f, D = 0.f;
        #pragma unroll
        for (int w = 0; w < NWRP; w++) { S += red[NWRP + w]; D += red[2 * NWRP + w]; }
        out[b] = D / S + pb[0];
    }
}

extern "C" void kernel_launch(void* const* d_in, const int* in_sizes, int n_in,
                              void* d_out, int out_size) {
    const float* x  = (const float*)d_in[0];
    const float* ww = (const float*)d_in[1];
    const float* wb = (const float*)d_in[2];
    const float* hw = (const float*)d_in[3];
    // d_in[4] = attn_h_b: uniform shift on scores, softmax-invariant -> unused
    const float* pw = (const float*)d_in[5];
    const float* pb = (const float*)d_in[6];
    float* out = (float*)d_out;

    int B = in_sizes[0] / (NF * ED);
    cudaFuncSetAttribute(afm_kernel, cudaFuncAttributeMaxDynamicSharedMemorySize, SMEM_SZ);
    afm_kernel<<<B, NTHR, SMEM_SZ>>>(x, ww, wb, hw, pw, pb, out);
}

// round 6
// speedup vs baseline: 1.2321x; 1.2200x over previous
#include <cuda_runtime.h>
#include <cstdint>

#define NF   40
#define ED   128
#define AD   128
#define NP   780     // 40*39/2
#define NPP  784     // 98 n-tiles of 8 pairs
#define NTHR 384     // 12 warps = 3 pair-groups x 4 a-slots
#define NWRP 12
#define XST  132     // padded row stride for x in smem (floats); 528B, 16B-aligned

__device__ __forceinline__ uint32_t tf32_of(float f) {
    uint32_t r;
    asm("cvt.rna.tf32.f32 %0, %1;" : "=r"(r) : "f"(f));
    return r;
}

// D(m16n8) += A(m16k8, tf32, row) * B(k8n8, tf32, col), fp32 accum
__device__ __forceinline__ void mma8(float* d, const uint32_t* a, float b0f, float b1f) {
    uint32_t b0 = __float_as_uint(b0f), b1 = __float_as_uint(b1f);  // raw f32 bits as tf32
    asm volatile(
        "mma.sync.aligned.m16n8k8.row.col.f32.tf32.tf32.f32 "
        "{%0,%1,%2,%3}, {%4,%5,%6,%7}, {%8,%9}, {%0,%1,%2,%3};"
        : "+f"(d[0]), "+f"(d[1]), "+f"(d[2]), "+f"(d[3])
        : "r"(a[0]), "r"(a[1]), "r"(a[2]), "r"(a[3]), "r"(b0), "r"(b1));
}

__global__ void __launch_bounds__(NTHR, 1)
afm_kernel(const float* __restrict__ x,    // [B, F, E]
           const float* __restrict__ ww,   // [A, E]
           const float* __restrict__ wb,   // [A]
           const float* __restrict__ hw,   // [1, A]
           const float* __restrict__ pw,   // [1, E]
           const float* __restrict__ pb,   // [1]
           float* __restrict__ out)        // [B]
{
    __shared__ float   xs[NF * XST];      // ~21.1 KB, row-major padded
    __shared__ float   scs4[4][NPP];      // per-aslot partial scores
    __shared__ float   scs[NPP];
    __shared__ float   dvs[NPP];          // d[p] = hp_p . p_w
    __shared__ float   pws[ED];
    __shared__ uint8_t pis[NPP], pjs[NPP];
    __shared__ float   red[3 * NWRP];

    const int tid  = threadIdx.x;
    const int wid  = tid >> 5, lane = tid & 31;
    const int g     = wid >> 2;       // pair-group 0..2
    const int aslot = wid & 3;        // owns a-rows [aslot*32, +32)
    const int q = lane >> 2, c = lane & 3;
    const int b = blockIdx.x;

    // ---- Stage x (row-major, padded stride) ----
    const float* xg = x + (size_t)b * (NF * ED);
    for (int idx = tid; idx < NF * ED; idx += NTHR)
        xs[(idx >> 7) * XST + (idx & 127)] = xg[idx];
    for (int e = tid; e < ED; e += NTHR) pws[e] = pw[e];

    // ---- Pair index tables (triu i<j, i-major) ----
    for (int p = tid; p < NPP; p += NTHR) {
        if (p < NP) {
            int i = 0, rem = p;
            while (rem >= NF - 1 - i) { rem -= NF - 1 - i; i++; }
            pis[p] = (uint8_t)i; pjs[p] = (uint8_t)(i + 1 + rem);
        } else { pis[p] = 0; pjs[p] = 1; }
    }

    // ---- W fragments (register-stationary), e-permuted to the segment map:
    //      step s=2u+t: logical k=c  <-> e = 16u + 4c + 2t
    //                   logical k=c+4 <-> e + 1
    const int A0 = aslot * 32;
    uint32_t wA[2][16][4];
    #pragma unroll
    for (int mt = 0; mt < 2; mt++) {
        #pragma unroll
        for (int s = 0; s < 16; s++) {
            int e  = 16 * (s >> 1) + 4 * c + 2 * (s & 1);
            int r0 = (A0 + mt * 16 + q) * ED + e;
            int r1 = r0 + 8 * ED;
            float2 w0 = *(const float2*)&ww[r0];
            float2 w1 = *(const float2*)&ww[r1];
            wA[mt][s][0] = tf32_of(w0.x);
            wA[mt][s][1] = tf32_of(w1.x);
            wA[mt][s][2] = tf32_of(w0.y);
            wA[mt][s][3] = tf32_of(w1.y);
        }
    }
    float wbr[4], hr[4];
    #pragma unroll
    for (int u = 0; u < 4; u++) {
        wbr[u] = wb[A0 + u * 8 + q];
        hr[u]  = hw[A0 + u * 8 + q];
    }

    __syncthreads();

    // ---- Main loop: n-tiles of 8 pairs; group g covers [g*33, min(g*33+33, 98)) ----
    const int nt0 = g * 33;
    const int nt1 = (g == 2) ? 98 : nt0 + 33;
    for (int nt = nt0; nt < nt1; nt++) {
        const int p = nt * 8 + q;                 // this quad's pair (B col)
        const float* xi = &xs[(int)pis[p] * XST + 4 * c];
        const float* xj = &xs[(int)pjs[p] * XST + 4 * c];

        float acc0[4] = {0.f, 0.f, 0.f, 0.f};
        float acc1[4] = {0.f, 0.f, 0.f, 0.f};
        #pragma unroll
        for (int u = 0; u < 8; u++) {
            float4 vi = *(const float4*)&xi[16 * u];
            float4 vj = *(const float4*)&xj[16 * u];
            float p0 = vi.x * vj.x, p1 = vi.y * vj.y;
            float p2 = vi.z * vj.z, p3 = vi.w * vj.w;
            mma8(acc0, wA[0][2 * u],     p0, p1);
            mma8(acc1, wA[1][2 * u],     p0, p1);
            mma8(acc0, wA[0][2 * u + 1], p2, p3);
            mma8(acc1, wA[1][2 * u + 1], p2, p3);
        }

        // Fused epilogue: partial score = sum over this warp's 32 a of h*relu(.+wb)
        float s0 = fmaxf(acc0[0] + wbr[0], 0.f) * hr[0]
                 + fmaxf(acc0[2] + wbr[1], 0.f) * hr[1]
                 + fmaxf(acc1[0] + wbr[2], 0.f) * hr[2]
                 + fmaxf(acc1[2] + wbr[3], 0.f) * hr[3];
        float s1 = fmaxf(acc0[1] + wbr[0], 0.f) * hr[0]
                 + fmaxf(acc0[3] + wbr[1], 0.f) * hr[1]
                 + fmaxf(acc1[1] + wbr[2], 0.f) * hr[2]
                 + fmaxf(acc1[3] + wbr[3], 0.f) * hr[3];
        #pragma unroll
        for (int o = 4; o <= 16; o <<= 1) {
            s0 += __shfl_xor_sync(0xffffffffu, s0, o);
            s1 += __shfl_xor_sync(0xffffffffu, s1, o);
        }
        if (lane < 4) {
            scs4[aslot][nt * 8 + 2 * lane]     = s0;
            scs4[aslot][nt * 8 + 2 * lane + 1] = s1;
        }
    }

    // ---- d[p] = sum_e x_i,e * x_j,e * pw_e (warp per pair) ----
    for (int p = wid; p < NP; p += NWRP) {
        const float* xi = &xs[(int)pis[p] * XST];
        const float* xj = &xs[(int)pjs[p] * XST];
        float a = 0.f;
        #pragma unroll
        for (int k = 0; k < 4; k++) {
            int e = lane + 32 * k;
            a = fmaf(xi[e] * xj[e], pws[e], a);
        }
        #pragma unroll
        for (int o = 16; o; o >>= 1) a += __shfl_xor_sync(0xffffffffu, a, o);
        if (lane == 0) dvs[p] = a;
    }
    __syncthreads();

    for (int p = tid; p < NP; p += NTHR)
        scs[p] = scs4[0][p] + scs4[1][p] + scs4[2][p] + scs4[3][p];
    __syncthreads();

    // ---- Softmax over pairs + weighted sum (h_b softmax-invariant, dropped) ----
    float lmax = -3.4e38f;
    for (int p = tid; p < NP; p += NTHR) lmax = fmaxf(lmax, scs[p]);
    #pragma unroll
    for (int o = 16; o; o >>= 1) lmax = fmaxf(lmax, __shfl_xor_sync(0xffffffffu, lmax, o));
    if (lane == 0) red[wid] = lmax;
    __syncthreads();
    float m = red[0];
    #pragma unroll
    for (int w = 1; w < NWRP; w++) m = fmaxf(m, red[w]);

    float se = 0.f, sd = 0.f;
    for (int p = tid; p < NP; p += NTHR) {
        float e = __expf(scs[p] - m);
        se += e;
        sd = fmaf(e, dvs[p], sd);
    }
    #pragma unroll
    for (int o = 16; o; o >>= 1) {
        se += __shfl_xor_sync(0xffffffffu, se, o);
        sd += __shfl_xor_sync(0xffffffffu, sd, o);
    }
    if (lane == 0) { red[NWRP + wid] = se; red[2 * NWRP + wid] = sd; }
    __syncthreads();
    if (tid == 0) {
        float S = 0.f, D = 0.f;
        #pragma unroll
        for (int w = 0; w < NWRP; w++) { S += red[NWRP + w]; D += red[2 * NWRP + w]; }
        out[b] = D / S + pb[0];
    }
}

extern "C" void kernel_launch(void* const* d_in, const int* in_sizes, int n_in,
                              void* d_out, int out_size) {
    const float* x  = (const float*)d_in[0];
    const float* ww = (const float*)d_in[1];
    const float* wb = (const float*)d_in[2];
    const float* hw = (const float*)d_in[3];
    // d_in[4] = attn_h_b: uniform shift on scores, softmax-invariant -> unused
    const float* pw = (const float*)d_in[5];
    const float* pb = (const float*)d_in[6];
    float* out = (float*)d_out;

    int B = in_sizes[0] / (NF * ED);
    afm_kernel<<<B, NTHR>>>(x, ww, wb, hw, pw, pb, out);
}

// round 7
// speedup vs baseline: 1.3355x; 1.0839x over previous
#include <cuda_runtime.h>
#include <cstdint>

#define NF   40
#define ED   128
#define AD   128
#define NP   780     // 40*39/2
#define NPP  784     // 98 n-tiles of 8 pairs
#define NTHR 384     // 12 warps = 3 pair-groups x 4 a-slots
#define NWRP 12
#define XST  132     // padded row stride for x in smem (floats); 528B, 16B-aligned

__device__ __forceinline__ uint32_t tf32_of(float f) {
    uint32_t r;
    asm("cvt.rna.tf32.f32 %0, %1;" : "=r"(r) : "f"(f));
    return r;
}

// D(m16n8) += A(m16k8, tf32, row) * B(k8n8, tf32, col), fp32 accum
__device__ __forceinline__ void mma8(float* d, const uint32_t* a, float b0f, float b1f) {
    uint32_t b0 = __float_as_uint(b0f), b1 = __float_as_uint(b1f);  // raw f32 bits as tf32
    asm volatile(
        "mma.sync.aligned.m16n8k8.row.col.f32.tf32.tf32.f32 "
        "{%0,%1,%2,%3}, {%4,%5,%6,%7}, {%8,%9}, {%0,%1,%2,%3};"
        : "+f"(d[0]), "+f"(d[1]), "+f"(d[2]), "+f"(d[3])
        : "r"(a[0]), "r"(a[1]), "r"(a[2]), "r"(a[3]), "r"(b0), "r"(b1));
}

__global__ void __launch_bounds__(NTHR, 1)
afm_kernel(const float* __restrict__ x,    // [B, F, E]
           const float* __restrict__ ww,   // [A, E]
           const float* __restrict__ wb,   // [A]
           const float* __restrict__ hw,   // [1, A]
           const float* __restrict__ pw,   // [1, E]
           const float* __restrict__ pb,   // [1]
           float* __restrict__ out)        // [B]
{
    __shared__ float   xs[NF * XST];      // ~21.1 KB, row-major padded
    __shared__ float   scs4[4][NPP];      // per-aslot partial scores
    __shared__ float   scs[NPP];
    __shared__ float   dvs[NPP];          // d[p] = hp_p . p_w
    __shared__ float   pws[ED];
    __shared__ uint8_t pis[NPP], pjs[NPP];
    __shared__ float   red[3 * NWRP];

    const int tid  = threadIdx.x;
    const int wid  = tid >> 5, lane = tid & 31;
    const int g     = wid >> 2;       // pair-group 0..2
    const int aslot = wid & 3;        // owns a-rows [aslot*32, +32)
    const int q = lane >> 2, c = lane & 3;
    const int b = blockIdx.x;

    // ---- Stage x (row-major, padded stride) ----
    const float* xg = x + (size_t)b * (NF * ED);
    for (int idx = tid; idx < NF * ED; idx += NTHR)
        xs[(idx >> 7) * XST + (idx & 127)] = xg[idx];
    for (int e = tid; e < ED; e += NTHR) pws[e] = pw[e];

    // ---- Pair index tables (triu i<j, i-major) ----
    for (int p = tid; p < NPP; p += NTHR) {
        if (p < NP) {
            int i = 0, rem = p;
            while (rem >= NF - 1 - i) { rem -= NF - 1 - i; i++; }
            pis[p] = (uint8_t)i; pjs[p] = (uint8_t)(i + 1 + rem);
        } else { pis[p] = 0; pjs[p] = 1; }
    }

    // ---- W fragments (register-stationary), e-permuted to the segment map:
    //      step s=2u+t: logical k=c   <-> e = 16u + 4c + 2t
    //                   logical k=c+4 <-> e + 1
    const int A0 = aslot * 32;
    uint32_t wA[2][16][4];
    #pragma unroll
    for (int mt = 0; mt < 2; mt++) {
        #pragma unroll
        for (int s = 0; s < 16; s++) {
            int e  = 16 * (s >> 1) + 4 * c + 2 * (s & 1);
            int r0 = (A0 + mt * 16 + q) * ED + e;
            int r1 = r0 + 8 * ED;
            float2 w0 = *(const float2*)&ww[r0];
            float2 w1 = *(const float2*)&ww[r1];
            wA[mt][s][0] = tf32_of(w0.x);
            wA[mt][s][1] = tf32_of(w1.x);
            wA[mt][s][2] = tf32_of(w0.y);
            wA[mt][s][3] = tf32_of(w1.y);
        }
    }

    __syncthreads();

    // ---- Main loop: n-tiles of 8 pairs; group g covers [g*33, min(g*33+33, 98)) ----
    const int nt0 = g * 33;
    const int nt1 = (g == 2) ? 98 : nt0 + 33;
    const bool do_d = (aslot == 0);   // this warp also accumulates d[p] = hp . pw

    for (int nt = nt0; nt < nt1; nt++) {
        const int p = nt * 8 + q;                 // this quad's pair (B col)
        const float* xi = &xs[(int)pis[p] * XST + 4 * c];
        const float* xj = &xs[(int)pjs[p] * XST + 4 * c];

        float acc0[4] = {0.f, 0.f, 0.f, 0.f};
        float acc1[4] = {0.f, 0.f, 0.f, 0.f};
        float dacc = 0.f;
        #pragma unroll
        for (int u = 0; u < 8; u++) {
            float4 vi = *(const float4*)&xi[16 * u];
            float4 vj = *(const float4*)&xj[16 * u];
            float p0 = vi.x * vj.x, p1 = vi.y * vj.y;
            float p2 = vi.z * vj.z, p3 = vi.w * vj.w;
            mma8(acc0, wA[0][2 * u],     p0, p1);
            mma8(acc1, wA[1][2 * u],     p0, p1);
            mma8(acc0, wA[0][2 * u + 1], p2, p3);
            mma8(acc1, wA[1][2 * u + 1], p2, p3);
            if (do_d) {
                float4 pw4 = *(const float4*)&pws[16 * u + 4 * c];
                dacc = fmaf(p0, pw4.x, fmaf(p1, pw4.y, fmaf(p2, pw4.z, fmaf(p3, pw4.w, dacc))));
            }
        }
        if (do_d) {
            dacc += __shfl_xor_sync(0xffffffffu, dacc, 1);
            dacc += __shfl_xor_sync(0xffffffffu, dacc, 2);
            if (c == 0 && p < NP) dvs[p] = dacc;
        }

        // Fused epilogue: partial score = sum over this warp's 32 a of h*relu(.+wb)
        float s0 = 0.f, s1 = 0.f;
        #pragma unroll
        for (int u = 0; u < 4; u++) {
            int a = A0 + u * 8 + q;
            float wbu = __ldg(&wb[a]);
            float hu  = __ldg(&hw[a]);
            float au0 = (u < 2) ? acc0[2 * u]     : acc1[2 * (u - 2)];
            float au1 = (u < 2) ? acc0[2 * u + 1] : acc1[2 * (u - 2) + 1];
            s0 += fmaxf(au0 + wbu, 0.f) * hu;
            s1 += fmaxf(au1 + wbu, 0.f) * hu;
        }
        #pragma unroll
        for (int o = 4; o <= 16; o <<= 1) {
            s0 += __shfl_xor_sync(0xffffffffu, s0, o);
            s1 += __shfl_xor_sync(0xffffffffu, s1, o);
        }
        if (lane < 4) {
            scs4[aslot][nt * 8 + 2 * lane]     = s0;
            scs4[aslot][nt * 8 + 2 * lane + 1] = s1;
        }
    }
    __syncthreads();

    for (int p = tid; p < NP; p += NTHR)
        scs[p] = scs4[0][p] + scs4[1][p] + scs4[2][p] + scs4[3][p];
    __syncthreads();

    // ---- Softmax over pairs + weighted sum (h_b softmax-invariant, dropped) ----
    float lmax = -3.4e38f;
    for (int p = tid; p < NP; p += NTHR) lmax = fmaxf(lmax, scs[p]);
    #pragma unroll
    for (int o = 16; o; o >>= 1) lmax = fmaxf(lmax, __shfl_xor_sync(0xffffffffu, lmax, o));
    if (lane == 0) red[wid] = lmax;
    __syncthreads();
    float m = red[0];
    #pragma unroll
    for (int w = 1; w < NWRP; w++) m = fmaxf(m, red[w]);

    float se = 0.f, sd = 0.f;
    for (int p = tid; p < NP; p += NTHR) {
        float e = __expf(scs[p] - m);
        se += e;
        sd = fmaf(e, dvs[p], sd);
    }
    #pragma unroll
    for (int o = 16; o; o >>= 1) {
        se += __shfl_xor_sync(0xffffffffu, se, o);
        sd += __shfl_xor_sync(0xffffffffu, sd, o);
    }
    if (lane == 0) { red[NWRP + wid] = se; red[2 * NWRP + wid] = sd; }
    __syncthreads();
    if (tid == 0) {
        float S = 0.f, D = 0.f;
        #pragma unroll
        for (int w = 0; w < NWRP; w++) { S += red[NWRP + w]; D += red[2 * NWRP + w]; }
        out[b] = D / S + pb[0];
    }
}

extern "C" void kernel_launch(void* const* d_in, const int* in_sizes, int n_in,
                              void* d_out, int out_size) {
    const float* x  = (const float*)d_in[0];
    const float* ww = (const float*)d_in[1];
    const float* wb = (const float*)d_in[2];
    const float* hw = (const float*)d_in[3];
    // d_in[4] = attn_h_b: uniform shift on scores, softmax-invariant -> unused
    const float* pw = (const float*)d_in[5];
    const float* pb = (const float*)d_in[6];
    float* out = (float*)d_out;

    int B = in_sizes[0] / (NF * ED);
    afm_kernel<<<B, NTHR>>>(x, ww, wb, hw, pw, pb, out);
}